// round 11
// baseline (speedup 1.0000x reference)
#include <cuda_runtime.h>
#include <math.h>

#define N 320
#define D 128
#define NMAT 3
#define RHO_C 10.0f
#define MARGIN_C 0.2f
#define TAU_C 1.3f
#define SEMIHARD_THRESH_C 0.01f
#define EPS_C 1e-12f
#define NTRI  210                // 20*21/2 lower-triangle 16x16 tiles
#define KCH   160                // k-chunk size (N/2)
#define BIG_C 1e30f

typedef unsigned long long ull;

// ---------------- device scratch (no allocations allowed) ----------------
__device__ float  g_d[NMAT][N][N];   // pairwise distances per matrix
__device__ float2 g_mm[2][N][N];     // per-chunk (maxs, minn) partials
__device__ float  g_pden[N];         // per-i row sums of pw
__device__ float  g_pnum[N];         // per-i sums of pos*pair_w
__device__ unsigned int g_cnt_i[N];  // per-i chunk tickets
__device__ unsigned int g_counter;   // global ticket for fused final

// ---------------- packed f32x2 helpers (per-lane bit-identical to scalar) ---
__device__ __forceinline__ ull add2(ull a, ull b) {
    ull r; asm("add.rn.f32x2 %0, %1, %2;" : "=l"(r) : "l"(a), "l"(b)); return r;
}
__device__ __forceinline__ ull mul2(ull a, ull b) {
    ull r; asm("mul.rn.f32x2 %0, %1, %2;" : "=l"(r) : "l"(a), "l"(b)); return r;
}
__device__ __forceinline__ ull fma2(ull a, ull b, ull c) {
    ull r; asm("fma.rn.f32x2 %0, %1, %2, %3;" : "=l"(r) : "l"(a), "l"(b), "l"(c)); return r;
}
__device__ __forceinline__ ull pack2(float lo, float hi) {
    ull r; asm("mov.b64 %0, {%1, %2};" : "=l"(r) : "f"(lo), "f"(hi)); return r;
}
__device__ __forceinline__ void unpack2(ull p, float& lo, float& hi) {
    asm("mov.b64 {%0, %1}, %2;" : "=f"(lo), "=f"(hi) : "l"(p));
}

// ---------------- kernel 1: distances; 630 blocks = 210 tiles x 3 mats ------
// (round-9 version: benched best; 16x16 tiles, high block count)
#define PADW 132
__global__ void __launch_bounds__(256) k_dist(const float* __restrict__ src,
                                              const float* __restrict__ emb) {
    int b  = blockIdx.x;
    int m  = b / NTRI;
    int bt = b - m * NTRI;
    int bi = (int)((sqrtf(8.0f * (float)bt + 1.0f) - 1.0f) * 0.5f);
    while ((bi + 1) * (bi + 2) / 2 <= bt) bi++;
    while (bi * (bi + 1) / 2 > bt) bi--;
    int bj = bt - bi * (bi + 1) / 2;
    int i0 = bi * 16, j0 = bj * 16;

    __shared__ float Ai[16][PADW];
    __shared__ float Aj[16][PADW];
    __shared__ float s_sq[32];
    __shared__ float s_ri[32];

    int t  = threadIdx.x;
    int tx = t & 15, ty = t >> 4;
    int lane = t & 31, warp = t >> 5;
    int i = i0 + ty, j = j0 + tx;

    if (b == 0) {                       // reset tickets (precedes k_tripart)
        if (t == 0) g_counter = 0;
        for (int e = t; e < N; e += 256) g_cnt_i[e] = 0;
    }

    const float* base = (m < 2) ? (src + (size_t)m * N * D) : emb;
    for (int e = t; e < 16 * 32; e += 256) {
        int r = e >> 5, c4 = e & 31;
        *(float4*)&Ai[r][c4 * 4] = ((const float4*)(base + (size_t)(i0 + r) * D))[c4];
        *(float4*)&Aj[r][c4 * 4] = ((const float4*)(base + (size_t)(j0 + r) * D))[c4];
    }
    __syncthreads();

    #pragma unroll
    for (int rr = 0; rr < 4; rr++) {
        int row = warp * 4 + rr;
        const float* rp = (row < 16) ? &Ai[row][0] : &Aj[row - 16][0];
        float4 x = ((const float4*)rp)[lane];
        float ssum = x.x * x.x + x.y * x.y + x.z * x.z + x.w * x.w;
        #pragma unroll
        for (int o = 16; o > 0; o >>= 1) ssum += __shfl_xor_sync(0xffffffffu, ssum, o);
        if (lane == 0) {
            float rn = 1.0f / fmaxf(sqrtf(ssum), EPS_C);
            s_sq[row] = ssum * (rn * rn);
            s_ri[row] = rn;
        }
    }
    __syncthreads();

    const float4* ai = (const float4*)&Ai[ty][0];
    const float4* aj = (const float4*)&Aj[tx][0];
    float d0 = 0.f, d1 = 0.f, d2a = 0.f, d3 = 0.f;
    #pragma unroll 8
    for (int c = 0; c < 32; c++) {
        float4 a = ai[c];
        float4 bb = aj[c];
        d0  += a.x * bb.x;
        d1  += a.y * bb.y;
        d2a += a.z * bb.z;
        d3  += a.w * bb.w;
    }
    float dot = (d0 + d1) + (d2a + d3);
    float rij = s_ri[ty] * s_ri[16 + tx];
    float dd  = s_sq[ty] + s_sq[16 + tx] - 2.0f * (dot * rij);
    float d   = sqrtf(fmaxf(dd, 0.0f) + EPS_C);
    g_d[m][i][j] = d;
    if (bi != bj) g_d[m][j][i] = d;    // bitwise symmetric by construction
}

// ---------------- kernel 2: split-k triplet (f32x2, branchless) -------------
// grid: 640 blocks (i = bx>>1, kc = bx&1), 320 threads (one per j).
// Value-ternary selects (FSEL) replace if/else: no BSSY/BSYNC divergence cost.
// launch_bounds(N,1) frees registers; 1-deep prefetch hides 29-cyc LDS latency.
__global__ void __launch_bounds__(N, 1) k_tripart(float* __restrict__ out) {
    int i  = blockIdx.x >> 1;
    int kc = blockIdx.x & 1;
    int t  = threadIdx.x;          // j

    __shared__ __align__(16) float sndk[N + 8];   // -d_emb[i][k]  (+pad for prefetch)
    __shared__ __align__(16) float sbk[N + 8];    // 1 - pw[i][k]
    __shared__ __align__(16) float srbk[N + 8];   // RHO * bk

    // prologue: each thread computes its own column's pw
    float d0j = g_d[0][i][t];
    float d1j = g_d[1][i][t];
    float dij = g_d[2][i][t];
    float pwij = 1.0f / (1.0f + expf(-RHO_C * (TAU_C - 0.5f * (d0j + d1j))));
    float bkj = 1.0f - pwij;
    sndk[t] = -dij;
    sbk[t]  = bkj;
    srbk[t] = RHO_C * bkj;
    if (t < 8) { sndk[N + t] = 0.0f; sbk[N + t] = 0.0f; srbk[N + t] = 0.0f; }
    __syncthreads();

    ull dij2 = pack2(dij, dij);
    ull M2   = pack2(MARGIN_C, MARGIN_C);
    ull npw2 = pack2(-pwij, -pwij);

    float mx0 = 0.0f, mx1 = 0.0f, mx2 = 0.0f, mx3 = 0.0f;
    float mn0 = BIG_C, mn1 = BIG_C, mn2 = BIG_C, mn3 = BIG_C;

    const ulonglong2* pnd = (const ulonglong2*)&sndk[kc * KCH];
    const ulonglong2* pbk = (const ulonglong2*)&sbk[kc * KCH];
    const ulonglong2* prb = (const ulonglong2*)&srbk[kc * KCH];

    // Per lane: t = dij + (-dk) == -(dk - dij) bitwise; m = M + t == M - diff.
    // k==j -> t==0 exactly -> m==0.2f exactly -> semihard (m <= MARGIN).
    ulonglong2 nd = pnd[0], bb = pbk[0], rr = prb[0];
    #pragma unroll 4
    for (int q = 0; q < KCH / 4; q++) {
        ulonglong2 ndn = pnd[q + 1];   // pad makes last prefetch safe
        ulonglong2 bbn = pbk[q + 1];
        ulonglong2 rrn = prb[q + 1];
        {
            ull t2  = add2(dij2, nd.x);
            ull m2  = add2(M2, t2);
            ull vs2 = mul2(m2, bb.x);
            ull vh2 = fma2(rr.x, npw2, m2);
            float m0, m1, vs0, vs1, vh0, vh1;
            unpack2(m2, m0, m1); unpack2(vs2, vs0, vs1); unpack2(vh2, vh0, vh1);
            mx0 = fmaxf(mx0, (m0 <= MARGIN_C) ? vs0 : 0.0f);
            mn0 = fminf(mn0, (m0 <= MARGIN_C) ? BIG_C : vh0);
            mx1 = fmaxf(mx1, (m1 <= MARGIN_C) ? vs1 : 0.0f);
            mn1 = fminf(mn1, (m1 <= MARGIN_C) ? BIG_C : vh1);
        }
        {
            ull t2  = add2(dij2, nd.y);
            ull m2  = add2(M2, t2);
            ull vs2 = mul2(m2, bb.y);
            ull vh2 = fma2(rr.y, npw2, m2);
            float m0, m1, vs0, vs1, vh0, vh1;
            unpack2(m2, m0, m1); unpack2(vs2, vs0, vs1); unpack2(vh2, vh0, vh1);
            mx2 = fmaxf(mx2, (m0 <= MARGIN_C) ? vs0 : 0.0f);
            mn2 = fminf(mn2, (m0 <= MARGIN_C) ? BIG_C : vh0);
            mx3 = fmaxf(mx3, (m1 <= MARGIN_C) ? vs1 : 0.0f);
            mn3 = fminf(mn3, (m1 <= MARGIN_C) ? BIG_C : vh1);
        }
        nd = ndn; bb = bbn; rr = rrn;
    }
    float maxs = fmaxf(fmaxf(mx0, mx1), fmaxf(mx2, mx3));  // assoc+comm: bit-exact
    float minn = fminf(fminf(mn0, mn1), fminf(mn2, mn3));

    __stcg(&g_mm[kc][i][t], make_float2(maxs, minn));
    __threadfence();

    // per-i ticket: second chunk block to finish combines row i
    __shared__ bool win_i;
    if (t == 0) win_i = (atomicAdd(&g_cnt_i[i], 1u) == 1u);
    __syncthreads();
    if (!win_i) return;

    float2 a = __ldcg(&g_mm[0][i][t]);
    float2 b = __ldcg(&g_mm[1][i][t]);
    float mx = fmaxf(a.x, b.x);
    float mn = fminf(a.y, b.y);
    float psh = pwij * mx;                          // pos_semihard
    float ph  = (mn < 0.0f) ? (mn + RHO_C) : 0.0f;
    float pos = psh + ((psh <= SEMIHARD_THRESH_C) ? ph : 0.0f);
    float contrib = pos * pwij;

    // deterministic dual block reduction: contrib (num) and pwij (den)
    float v = contrib, w = pwij;
    #pragma unroll
    for (int o = 16; o > 0; o >>= 1) {
        v += __shfl_down_sync(0xffffffffu, v, o);
        w += __shfl_down_sync(0xffffffffu, w, o);
    }
    __shared__ float swn[10], swd[10];
    int lane = t & 31, warp = t >> 5;
    if (lane == 0) { swn[warp] = v; swd[warp] = w; }
    __syncthreads();
    if (warp == 0 && lane == 0) {
        float sn = 0.0f, sd = 0.0f;
        #pragma unroll
        for (int q = 0; q < 10; q++) { sn += swn[q]; sd += swd[q]; }
        g_pnum[i] = sn;
        g_pden[i] = sd;
    }

    // ---- fused final: last winning block sums everything ----
    __threadfence();
    __shared__ bool is_last;
    if (t == 0) is_last = (atomicAdd(&g_counter, 1u) == (unsigned)(N - 1));
    __syncthreads();
    if (!is_last) return;

    float num = __ldcg(&g_pnum[t]);
    float den = __ldcg(&g_pden[t]);
    #pragma unroll
    for (int o = 16; o > 0; o >>= 1) {
        num += __shfl_down_sync(0xffffffffu, num, o);
        den += __shfl_down_sync(0xffffffffu, den, o);
    }
    __shared__ float sn2[10], sd2[10];
    if (lane == 0) { sn2[warp] = num; sd2[warp] = den; }
    __syncthreads();
    if (t == 0) {
        float fn = 0.0f, fd = 0.0f;
        #pragma unroll
        for (int q = 0; q < 10; q++) { fn += sn2[q]; fd += sd2[q]; }
        out[0] = (fd > 0.0f) ? (fn / fmaxf(fd, EPS_C)) : 0.0f;
    }
}

extern "C" void kernel_launch(void* const* d_in, const int* in_sizes, int n_in,
                              void* d_out, int out_size) {
    (void)n_in; (void)out_size;
    const float* src = (const float*)d_in[0];
    const float* emb = (const float*)d_in[1];
    if (n_in >= 2 && in_sizes[0] == N * D && in_sizes[1] == 2 * N * D) {
        const float* tmp = src; src = emb; emb = tmp;
    }
    float* out = (float*)d_out;

    k_dist<<<NMAT * NTRI, 256>>>(src, emb);
    k_tripart<<<2 * N, N>>>(out);
}

// round 12
// speedup vs baseline: 1.2058x; 1.2058x over previous
#include <cuda_runtime.h>
#include <math.h>

#define N 320
#define D 128
#define NMAT 3
#define RHO_C 10.0f
#define MARGIN_C 0.2f
#define TAU_C 1.3f
#define SEMIHARD_THRESH_C 0.01f
#define EPS_C 1e-12f
#define NTRI  210                // 20*21/2 lower-triangle 16x16 tiles
#define KCH   160                // k-chunk size (N/2)

typedef unsigned long long ull;

// ---------------- device scratch (no allocations allowed) ----------------
__device__ float  g_d[NMAT][N][N];   // pairwise distances per matrix
__device__ float2 g_mm[2][N][N];     // per-chunk (maxs, minn) partials
__device__ float  g_pden[N];         // per-i row sums of pw
__device__ float  g_pnum[N];         // per-i sums of pos*pair_w
__device__ unsigned int g_cnt_i[N];  // per-i chunk tickets
__device__ unsigned int g_counter;   // global ticket for fused final

// ---------------- packed f32x2 helpers (per-lane bit-identical to scalar) ---
__device__ __forceinline__ ull add2(ull a, ull b) {
    ull r; asm("add.rn.f32x2 %0, %1, %2;" : "=l"(r) : "l"(a), "l"(b)); return r;
}
__device__ __forceinline__ ull mul2(ull a, ull b) {
    ull r; asm("mul.rn.f32x2 %0, %1, %2;" : "=l"(r) : "l"(a), "l"(b)); return r;
}
__device__ __forceinline__ ull fma2(ull a, ull b, ull c) {
    ull r; asm("fma.rn.f32x2 %0, %1, %2, %3;" : "=l"(r) : "l"(a), "l"(b), "l"(c)); return r;
}
__device__ __forceinline__ ull pack2(float lo, float hi) {
    ull r; asm("mov.b64 %0, {%1, %2};" : "=l"(r) : "f"(lo), "f"(hi)); return r;
}
__device__ __forceinline__ void unpack2(ull p, float& lo, float& hi) {
    asm("mov.b64 {%0, %1}, %2;" : "=f"(lo), "=f"(hi) : "l"(p));
}

// ---------------- kernel 1: distances; 630 blocks = 210 tiles x 3 mats ------
#define PADW 132
__global__ void __launch_bounds__(256) k_dist(const float* __restrict__ src,
                                              const float* __restrict__ emb) {
    int b  = blockIdx.x;
    int m  = b / NTRI;
    int bt = b - m * NTRI;
    int bi = (int)((sqrtf(8.0f * (float)bt + 1.0f) - 1.0f) * 0.5f);
    while ((bi + 1) * (bi + 2) / 2 <= bt) bi++;
    while (bi * (bi + 1) / 2 > bt) bi--;
    int bj = bt - bi * (bi + 1) / 2;
    int i0 = bi * 16, j0 = bj * 16;

    __shared__ float Ai[16][PADW];
    __shared__ float Aj[16][PADW];
    __shared__ float s_sq[32];
    __shared__ float s_ri[32];

    int t  = threadIdx.x;
    int tx = t & 15, ty = t >> 4;
    int lane = t & 31, warp = t >> 5;
    int i = i0 + ty, j = j0 + tx;

    if (b == 0) {                       // reset tickets (precedes k_tripart)
        if (t == 0) g_counter = 0;
        for (int e = t; e < N; e += 256) g_cnt_i[e] = 0;
    }

    const float* base = (m < 2) ? (src + (size_t)m * N * D) : emb;
    for (int e = t; e < 16 * 32; e += 256) {
        int r = e >> 5, c4 = e & 31;
        *(float4*)&Ai[r][c4 * 4] = ((const float4*)(base + (size_t)(i0 + r) * D))[c4];
        *(float4*)&Aj[r][c4 * 4] = ((const float4*)(base + (size_t)(j0 + r) * D))[c4];
    }
    __syncthreads();

    #pragma unroll
    for (int rr = 0; rr < 4; rr++) {
        int row = warp * 4 + rr;
        const float* rp = (row < 16) ? &Ai[row][0] : &Aj[row - 16][0];
        float4 x = ((const float4*)rp)[lane];
        float ssum = x.x * x.x + x.y * x.y + x.z * x.z + x.w * x.w;
        #pragma unroll
        for (int o = 16; o > 0; o >>= 1) ssum += __shfl_xor_sync(0xffffffffu, ssum, o);
        if (lane == 0) {
            float rn = 1.0f / fmaxf(sqrtf(ssum), EPS_C);
            s_sq[row] = ssum * (rn * rn);
            s_ri[row] = rn;
        }
    }
    __syncthreads();

    const float4* ai = (const float4*)&Ai[ty][0];
    const float4* aj = (const float4*)&Aj[tx][0];
    float d0 = 0.f, d1 = 0.f, d2a = 0.f, d3 = 0.f;
    #pragma unroll 8
    for (int c = 0; c < 32; c++) {
        float4 a = ai[c];
        float4 bb = aj[c];
        d0  += a.x * bb.x;
        d1  += a.y * bb.y;
        d2a += a.z * bb.z;
        d3  += a.w * bb.w;
    }
    float dot = (d0 + d1) + (d2a + d3);
    float rij = s_ri[ty] * s_ri[16 + tx];
    float dd  = s_sq[ty] + s_sq[16 + tx] - 2.0f * (dot * rij);
    float d   = sqrtf(fmaxf(dd, 0.0f) + EPS_C);
    g_d[m][i][j] = d;
    if (bi != bj) g_d[m][j][i] = d;    // bitwise symmetric by construction
}

// ---------------- kernel 2: split-k triplet (f32x2) + combine + final -------
// grid: 640 blocks (i = bx>>1, kc = bx&1), 320 threads (one per j).
// R9 core (predicated if/else — fastest measured) with only TWO smem streams:
// vh = fma(bk, -(RHO*pwij), m) replaces the rbk array (one less LDS.128/group).
__global__ void __launch_bounds__(N) k_tripart(float* __restrict__ out) {
    int i  = blockIdx.x >> 1;
    int kc = blockIdx.x & 1;
    int t  = threadIdx.x;          // j

    __shared__ __align__(16) float sndk[N];   // -d_emb[i][k]
    __shared__ __align__(16) float sbk[N];    // 1 - pw[i][k]

    // prologue: each thread computes its own column's pw
    float d0j = g_d[0][i][t];
    float d1j = g_d[1][i][t];
    float dij = g_d[2][i][t];
    float pwij = 1.0f / (1.0f + expf(-RHO_C * (TAU_C - 0.5f * (d0j + d1j))));
    float bkj = 1.0f - pwij;
    sndk[t] = -dij;
    sbk[t]  = bkj;
    __syncthreads();

    ull dij2  = pack2(dij, dij);
    ull M2    = pack2(MARGIN_C, MARGIN_C);
    float nrpw = -(RHO_C * pwij);
    ull nrpw2 = pack2(nrpw, nrpw);

    float mx0 = 0.0f, mx1 = 0.0f, mx2 = 0.0f, mx3 = 0.0f;
    float mn0 = 1e30f, mn1 = 1e30f, mn2 = 1e30f, mn3 = 1e30f;

    const ulonglong2* pnd = (const ulonglong2*)&sndk[kc * KCH];
    const ulonglong2* pbk = (const ulonglong2*)&sbk[kc * KCH];

    // Per lane: t = dij + (-dk) == -(dk - dij) bitwise; m = M + t == M - diff.
    // k==j -> t==0 exactly -> m==0.2f exactly -> semihard (m <= MARGIN).
    #pragma unroll 8
    for (int q = 0; q < KCH / 4; q++) {
        ulonglong2 nd = pnd[q];        // 4 k's of -dk
        ulonglong2 bb = pbk[q];        // 4 k's of bk
        {
            ull t2  = add2(dij2, nd.x);
            ull m2  = add2(M2, t2);
            ull vs2 = mul2(m2, bb.x);
            ull vh2 = fma2(bb.x, nrpw2, m2);
            float m0, m1, vs0, vs1, vh0, vh1;
            unpack2(m2, m0, m1); unpack2(vs2, vs0, vs1); unpack2(vh2, vh0, vh1);
            if (m0 <= MARGIN_C) mx0 = fmaxf(mx0, vs0); else mn0 = fminf(mn0, vh0);
            if (m1 <= MARGIN_C) mx1 = fmaxf(mx1, vs1); else mn1 = fminf(mn1, vh1);
        }
        {
            ull t2  = add2(dij2, nd.y);
            ull m2  = add2(M2, t2);
            ull vs2 = mul2(m2, bb.y);
            ull vh2 = fma2(bb.y, nrpw2, m2);
            float m0, m1, vs0, vs1, vh0, vh1;
            unpack2(m2, m0, m1); unpack2(vs2, vs0, vs1); unpack2(vh2, vh0, vh1);
            if (m0 <= MARGIN_C) mx2 = fmaxf(mx2, vs0); else mn2 = fminf(mn2, vh0);
            if (m1 <= MARGIN_C) mx3 = fmaxf(mx3, vs1); else mn3 = fminf(mn3, vh1);
        }
    }
    float maxs = fmaxf(fmaxf(mx0, mx1), fmaxf(mx2, mx3));  // assoc+comm: bit-exact
    float minn = fminf(fminf(mn0, mn1), fminf(mn2, mn3));

    __stcg(&g_mm[kc][i][t], make_float2(maxs, minn));
    __threadfence();

    // per-i ticket: second chunk block to finish combines row i
    __shared__ bool win_i;
    if (t == 0) win_i = (atomicAdd(&g_cnt_i[i], 1u) == 1u);
    __syncthreads();
    if (!win_i) return;

    float2 a = __ldcg(&g_mm[0][i][t]);
    float2 b = __ldcg(&g_mm[1][i][t]);
    float mx = fmaxf(a.x, b.x);
    float mn = fminf(a.y, b.y);
    float psh = pwij * mx;                          // pos_semihard
    float ph  = (mn < 0.0f) ? (mn + RHO_C) : 0.0f;
    float pos = psh + ((psh <= SEMIHARD_THRESH_C) ? ph : 0.0f);
    float contrib = pos * pwij;

    // deterministic dual block reduction: contrib (num) and pwij (den)
    float v = contrib, w = pwij;
    #pragma unroll
    for (int o = 16; o > 0; o >>= 1) {
        v += __shfl_down_sync(0xffffffffu, v, o);
        w += __shfl_down_sync(0xffffffffu, w, o);
    }
    __shared__ float swn[10], swd[10];
    int lane = t & 31, warp = t >> 5;
    if (lane == 0) { swn[warp] = v; swd[warp] = w; }
    __syncthreads();
    if (warp == 0 && lane == 0) {
        float sn = 0.0f, sd = 0.0f;
        #pragma unroll
        for (int q = 0; q < 10; q++) { sn += swn[q]; sd += swd[q]; }
        g_pnum[i] = sn;
        g_pden[i] = sd;
    }

    // ---- fused final: last winning block sums everything ----
    __threadfence();
    __shared__ bool is_last;
    if (t == 0) is_last = (atomicAdd(&g_counter, 1u) == (unsigned)(N - 1));
    __syncthreads();
    if (!is_last) return;

    float num = __ldcg(&g_pnum[t]);
    float den = __ldcg(&g_pden[t]);
    #pragma unroll
    for (int o = 16; o > 0; o >>= 1) {
        num += __shfl_down_sync(0xffffffffu, num, o);
        den += __shfl_down_sync(0xffffffffu, den, o);
    }
    __shared__ float sn2[10], sd2[10];
    if (lane == 0) { sn2[warp] = num; sd2[warp] = den; }
    __syncthreads();
    if (t == 0) {
        float fn = 0.0f, fd = 0.0f;
        #pragma unroll
        for (int q = 0; q < 10; q++) { fn += sn2[q]; fd += sd2[q]; }
        out[0] = (fd > 0.0f) ? (fn / fmaxf(fd, EPS_C)) : 0.0f;
    }
}

extern "C" void kernel_launch(void* const* d_in, const int* in_sizes, int n_in,
                              void* d_out, int out_size) {
    (void)n_in; (void)out_size;
    const float* src = (const float*)d_in[0];
    const float* emb = (const float*)d_in[1];
    if (n_in >= 2 && in_sizes[0] == N * D && in_sizes[1] == 2 * N * D) {
        const float* tmp = src; src = emb; emb = tmp;
    }
    float* out = (float*)d_out;

    k_dist<<<NMAT * NTRI, 256>>>(src, emb);
    k_tripart<<<2 * N, N>>>(out);
}